// round 11
// baseline (speedup 1.0000x reference)
#include <cuda_runtime.h>
#include <math.h>

#define GRID_H   48
#define NPTS     2304
#define NCH      16
#define NOFF     277       // in-circle window offsets (dr^2+dc^2 <= 88)
#define MAXE     84        // 64 valid max + 16 pad + margin
#define XSTRIDE  36864     // NPTS*NCH
#define NWARP    5

// Phase A + spline + compaction, warp-local.
// NR rounds; in the last round only lanes < NVL are valid.
template<int NR, int NVL>
__device__ __forceinline__ int phase_a(
    int lane, float inv_h, int ri, int ci, float xi, float yi,
    const int* __restrict__ drv, const int* __restrict__ dcv,
    const float* __restrict__ distv, const int* __restrict__ joffv,
    const float4* __restrict__ wva,            // per-warp (w2,w3,v,a) rows
    const float* __restrict__ sS, float b2, int ibase,
    float2* __restrict__ wjRow)
{
    const float inv47 = 1.0f / 47.0f;
    float xj[NR], yj[NR], acc[NR];
#pragma unroll
    for (int r = 0; r < NR; r++) {
        xj[r] = fmaf((float)drv[r], inv47, xi);
        yj[r] = fmaf((float)dcv[r], inv47, yi);
        acc[r] = 0.0f;
    }
#pragma unroll
    for (int k = 0; k < 32; k++) {
        float4 w = wva[k];    // LDS.128 broadcast
#pragma unroll
        for (int r = 0; r < NR; r++) {
            float t = fmaf(yj[r], w.y, fmaf(xj[r], w.x, w.w));
            acc[r] = fmaf(w.z, fmaxf(t, 0.0f), acc[r]);
        }
    }
    const float CKNOT = 1.0f / (1.0f / 15.0f + 1e-8f);
    int cnt = 0;
#pragma unroll
    for (int r = 0; r < NR; r++) {
        int rj = ri + drv[r];
        int cj = ci + dcv[r];
        bool ok = ((unsigned)rj < GRID_H) && ((unsigned)cj < GRID_H);
        if (r == NR - 1 && NVL < 32) ok = ok && (lane < NVL);
        unsigned m = __ballot_sync(0xffffffffu, ok);
        if (ok) {
            float rr  = fminf(distv[r] * inv_h, 1.0f);
            int   idx = min((int)(rr * 15.0f), 14);
            float wr  = (rr - (float)idx * (1.0f / 15.0f)) * CKNOT;
            float s0  = sS[idx];
            float psi = fmaf(wr, sS[idx + 1] - s0, s0);
            float w   = (acc[r] + b2) * psi;
            int  pos  = cnt + __popc(m & ((1u << lane) - 1u));
            wjRow[pos] = make_float2(w, __int_as_float(ibase + joffv[r]));
        }
        cnt += __popc(m);
    }
    return cnt;
}

__global__ __launch_bounds__(160, 8)
void si_blocks_kernel(const float* __restrict__ x,
                      const float* __restrict__ phi_w1, const float* __restrict__ phi_b1,
                      const float* __restrict__ phi_w2, const float* __restrict__ phi_b2,
                      const float* __restrict__ h_w1,  const float* __restrict__ h_b1,
                      const float* __restrict__ h_w2,  const float* __restrict__ h_b2,
                      const float* __restrict__ S_m,
                      float* __restrict__ out)
{
    __shared__ float  sW0[32], sW1[32], sB1[32];
    __shared__ float  sHW1a[32], sHW1b[32], sHB1[32], sHW2[32];
    __shared__ float  sS[16], sDist[89];
    __shared__ float  sB2v, sHB2v;
    __shared__ int    sOff[288];                 // packed (dr+9)<<5 | (dc+9)
    __shared__ float4 sWVA[NWARP][32];           // per-warp (w2,w3,v,a) rows
    __shared__ float2 sWJ[NWARP][MAXE];          // per-warp compacted lists
    __shared__ int    sCnt[NWARP];
    __shared__ float4 sPart[NWARP][8];

    const int tid  = threadIdx.x;
    const int sub  = tid >> 5;     // 5 warps
    const int lane = tid & 31;
    const float inv47 = 1.0f / 47.0f;

    // ---- block init ----
    if (tid < 16) sS[tid] = S_m[tid];
    if (tid >= 32 && tid < 64) {
        int l = tid - 32;
        sW0[l] = phi_w1[l]; sW1[l] = phi_w1[32 + l]; sB1[l] = phi_b1[l];
        sHW1a[l] = h_w1[l]; sHW1b[l] = h_w1[32 + l];
        sHB1[l] = h_b1[l];  sHW2[l] = h_w2[l];
    }
    if (tid == 16) sB2v  = phi_b2[0];
    if (tid == 17) sHB2v = h_b2[0];
    if (tid >= 64 && tid < 153) sDist[tid - 64] = sqrtf((float)(tid - 64)) * inv47;
    if (sub == 4) {   // light warp compacts in-circle offsets (deterministic order)
        int cnt = 0;
        for (int rr = 0; rr < 12; rr++) {
            int cand = lane + rr * 32;
            int q = cand / 19;
            int dr = q - 9, dc = cand - q * 19 - 9;
            bool ok = (cand < 361) && (dr * dr + dc * dc <= 88);
            unsigned m = __ballot_sync(0xffffffffu, ok);
            if (ok) sOff[cnt + __popc(m & ((1u << lane) - 1u))] = ((dr + 9) << 5) | (dc + 9);
            cnt += __popc(m);
        }
    }
    __syncthreads();

    // ---- per-lane persistent phi weights (k = lane) ----
    const float w2L = phi_w1[64 + lane];
    const float w3L = phi_w1[96 + lane];
    const float vL  = phi_w2[lane];

    // ---- per-warp slot geometry: contiguous chunks 64*4 + 21 ----
    int   drv[2], dcv[2], joffv[2];
    float distv[2];
#pragma unroll
    for (int r = 0; r < 2; r++) {
        int slot = min(sub * 64 + 32 * r + lane, NOFF - 1);
        int pk = sOff[slot];
        int dr = (pk >> 5) - 9, dc = (pk & 31) - 9;
        drv[r] = dr; dcv[r] = dc;
        distv[r] = sDist[dr * dr + dc * dc];
        joffv[r] = (dr * GRID_H + dc) * NCH;
    }

    const int   i  = blockIdx.x;
    const int   ri = i / GRID_H;
    const int   ci = i - ri * GRID_H;
    const float xi = (float)ri * inv47;
    const float yi = (float)ci * inv47;

    // h_net (warp-local, redundant; no barrier)
    float hz = fmaxf(fmaf(xi, sHW1a[lane], fmaf(yi, sHW1b[lane], sHB1[lane])), 0.0f)
               * sHW2[lane];
#pragma unroll
    for (int o = 16; o; o >>= 1) hz += __shfl_xor_sync(0xffffffffu, hz, o);
    hz += sHB2v;
    float hval  = fmaxf(hz, 0.0f) + log1pf(expf(-fabsf(hz)));
    float inv_h = 1.0f / (hval + 1e-6f);

    // per-i phi row: (w2,w3,v,a) for k = lane, one STS.128
    float aL = fmaf(xi, sW0[lane], fmaf(yi, sW1[lane], sB1[lane]));
    sWVA[sub][lane] = make_float4(w2L, w3L, vL, aL);
    __syncwarp();

    // Phase A + compact (warps 0-3: 2 full rounds; warp 4: 1 round, 21 lanes)
    float2* wjRow = sWJ[sub];
    int cnt;
    if (sub < 4)
        cnt = phase_a<2, 32>(lane, inv_h, ri, ci, xi, yi, drv, dcv, distv, joffv,
                             sWVA[sub], sS, sB2v, i * NCH, wjRow);
    else
        cnt = phase_a<1, 21>(lane, inv_h, ri, ci, xi, yi, drv, dcv, distv, joffv,
                             sWVA[sub], sS, sB2v, i * NCH, wjRow);
    if (lane < 16) wjRow[cnt + lane] = make_float2(0.0f, __int_as_float(0));
    if (lane == 0) sCnt[sub] = cnt;
    __syncwarp();

    // Phase B: 8 slots x 2 batches x 16 ch per iter, double-prefetched
    const int n2 = lane >> 3;
    const int bb = (lane >> 2) & 1;
    const int qq = lane & 3;
    const float* xq = x + bb * XSTRIDE + qq * 4;
    const int cnt8 = (cnt + 7) & ~7;
    float4 acc = make_float4(0.f, 0.f, 0.f, 0.f);
    float2 wj0 = wjRow[n2];
    float2 wj1 = wjRow[4 + n2];
    for (int t = 0; t < cnt8; t += 8) {
        float2 p0 = wjRow[t + 8 + n2];
        float2 p1 = wjRow[t + 12 + n2];
        float4 v0 = *reinterpret_cast<const float4*>(xq + __float_as_int(wj0.y));
        float4 v1 = *reinterpret_cast<const float4*>(xq + __float_as_int(wj1.y));
        acc.x = fmaf(wj0.x, v0.x, acc.x);
        acc.y = fmaf(wj0.x, v0.y, acc.y);
        acc.z = fmaf(wj0.x, v0.z, acc.z);
        acc.w = fmaf(wj0.x, v0.w, acc.w);
        acc.x = fmaf(wj1.x, v1.x, acc.x);
        acc.y = fmaf(wj1.x, v1.y, acc.y);
        acc.z = fmaf(wj1.x, v1.z, acc.z);
        acc.w = fmaf(wj1.x, v1.w, acc.w);
        wj0 = p0; wj1 = p1;
    }
#pragma unroll
    for (int o = 8; o <= 16; o <<= 1) {
        acc.x += __shfl_xor_sync(0xffffffffu, acc.x, o);
        acc.y += __shfl_xor_sync(0xffffffffu, acc.y, o);
        acc.z += __shfl_xor_sync(0xffffffffu, acc.z, o);
        acc.w += __shfl_xor_sync(0xffffffffu, acc.w, o);
    }
    if (lane < 8) sPart[sub][lane] = acc;
    __syncthreads();

    if (sub == 0 && lane < 8) {
        float4 s0 = sPart[0][lane];
        float4 s1 = sPart[1][lane];
        float4 s2 = sPart[2][lane];
        float4 s3 = sPart[3][lane];
        float4 s4 = sPart[4][lane];
        int tot = sCnt[0] + sCnt[1] + sCnt[2] + sCnt[3] + sCnt[4];
        float sc = 1.0f / (float)tot;
        float4 o;
        o.x = (s0.x + s1.x + s2.x + s3.x + s4.x) * sc;
        o.y = (s0.y + s1.y + s2.y + s3.y + s4.y) * sc;
        o.z = (s0.z + s1.z + s2.z + s3.z + s4.z) * sc;
        o.w = (s0.w + s1.w + s2.w + s3.w + s4.w) * sc;
        *reinterpret_cast<float4*>(out + bb * XSTRIDE + i * NCH + qq * 4) = o;
    }
}

extern "C" void kernel_launch(void* const* d_in, const int* in_sizes, int n_in,
                              void* d_out, int out_size)
{
    const float* x      = (const float*)d_in[0];
    const float* phi_w1 = (const float*)d_in[1];
    const float* phi_b1 = (const float*)d_in[2];
    const float* phi_w2 = (const float*)d_in[3];
    const float* phi_b2 = (const float*)d_in[4];
    const float* h_w1   = (const float*)d_in[5];
    const float* h_b1   = (const float*)d_in[6];
    const float* h_w2   = (const float*)d_in[7];
    const float* h_b2   = (const float*)d_in[8];
    const float* S_m    = (const float*)d_in[9];
    float* out = (float*)d_out;

    si_blocks_kernel<<<NPTS, 160>>>(
        x, phi_w1, phi_b1, phi_w2, phi_b2,
        h_w1, h_b1, h_w2, h_b2, S_m, out);
}